// round 10
// baseline (speedup 1.0000x reference)
#include <cuda_runtime.h>
#include <cstdint>

// ---------------------------------------------------------------------------
// PriorFusion3D_voxel — fp32 SIMT pipeline with packed f32x2 FMA (sm_103a)
//
// Pipeline:
//   0) zero voxel grid + permute conv1 weights (single fused launch)
//        g_vox [400][400][512] (k = z*64+c),  g_bw [256][512]
//   1) per-point MLP (68->64->64) + scatter -> g_vox
//   2) conv1 1x1 (512->256) +BN+ReLU (GEMM) -> g_p1  [256][400*400]  (NCHW)
//      K-tile 16, n-half-fastest grid (A shared via L2), reg-pipelined
//   3) conv2 3x3 (256->256) +BN+ReLU + fused 2x2 maxpool -> g_pool [256][200*200]
//      oc-group FASTEST grid dim (32x input-tile L2 reuse) + cp.async
//      double-buffered staging (stage s+1 copies overlap stage s compute)
//   4) concat(bev, pooled-reshaped) -> 1x1x1 conv (112->80) +BN + residual ReLU
// ---------------------------------------------------------------------------

#define NPOS   160000      // 400*400
#define PPOS   40000       // 200*200
#define OUTPOS 320000      // 200*200*8

__device__ __align__(16) float g_vox[400 * 400 * 512];    // 327.68 MB
__device__ __align__(16) float g_p1 [256 * NPOS];         // 163.84 MB
__device__ __align__(16) float g_pool[256 * PPOS];        //  40.96 MB
__device__ __align__(16) float g_bw [256 * 512];          //   0.52 MB (permuted c1w)

__device__ __forceinline__ float2 ffma2(float2 a, float2 b, float2 c) {
    float2 d;
    asm("fma.rn.f32x2 %0, %1, %2, %3;"
        : "=l"(reinterpret_cast<unsigned long long &>(d))
        : "l"(reinterpret_cast<unsigned long long &>(a)),
          "l"(reinterpret_cast<unsigned long long &>(b)),
          "l"(reinterpret_cast<unsigned long long &>(c)));
    return d;
}

__device__ __forceinline__ uint32_t smem_u32(const void *p) {
    return (uint32_t)__cvta_generic_to_shared(p);
}
// 4-byte async copy; src_bytes = 0 -> zero-fill (no global read per PTX spec)
__device__ __forceinline__ void cp_async4(uint32_t dst, const void *src, int src_bytes) {
    asm volatile("cp.async.ca.shared.global [%0], [%1], 4, %2;"
                 :: "r"(dst), "l"(src), "r"(src_bytes));
}

// ---------------------------------------------------------------------------
// Kernel 0 (fused): blocks [0, 80000) zero the voxel grid (exact float4
// coverage of 81,920,000 floats); blocks [80000, 80512) permute conv1
// weights into k-contiguous order:
//   g_bw[o][kk] = c1w[o][(kk&63)*8 + (kk>>6)]   (kk = z*64+c voxel k-order)
// ---------------------------------------------------------------------------
__global__ void k_zero_permw(const float *__restrict__ c1w) {
    if (blockIdx.x < 80000) {
        size_t i = ((size_t)blockIdx.x * blockDim.x + threadIdx.x) * 4;
        *reinterpret_cast<float4 *>(&g_vox[i]) = make_float4(0.f, 0.f, 0.f, 0.f);
    } else {
        int idx = (blockIdx.x - 80000) * 256 + threadIdx.x;   // 0 .. 131071
        int o  = idx >> 9;
        int kk = idx & 511;
        g_bw[idx] = c1w[(o << 9) + ((kk & 63) << 3) + (kk >> 6)];
    }
}

// ---------------------------------------------------------------------------
// Kernel 1: per-point MLP + scatter.  4 points/block, 64 threads/point.
// vox layout: g_vox[(cy*400+cx)*512 + cz*64 + c]
// ---------------------------------------------------------------------------
__global__ void k_mlp_scatter(const float *__restrict__ pf,
                              const int   *__restrict__ pc,
                              const float *__restrict__ W1,
                              const float *__restrict__ b1,
                              const float *__restrict__ W2,
                              const float *__restrict__ b2,
                              int N) {
    __shared__ float sx[4][68];
    __shared__ float sh[4][64];
    const int pt = threadIdx.x >> 6;
    const int j  = threadIdx.x & 63;
    const int p  = blockIdx.x * 4 + pt;
    const bool valid = (p < N);

    if (valid) {
        for (int i = j; i < 68; i += 64) sx[pt][i] = pf[p * 68 + i];
    }
    __syncthreads();

    float h1 = b1[j];
#pragma unroll
    for (int i = 0; i < 68; i++) h1 = fmaf(sx[pt][i], W1[i * 64 + j], h1);
    sh[pt][j] = fmaxf(h1, 0.f);
    __syncthreads();

    if (!valid) return;
    float h2 = b2[j];
#pragma unroll
    for (int i = 0; i < 64; i++) h2 = fmaf(sh[pt][i], W2[i * 64 + j], h2);
    h2 = fmaxf(h2, 0.f);

    const int cx = pc[p * 3 + 0], cy = pc[p * 3 + 1], cz = pc[p * 3 + 2];
    g_vox[((size_t)(cy * 400 + cx)) * 512 + cz * 64 + j] = h2;
}

// ---------------------------------------------------------------------------
// Kernel 2: conv1 as SGEMM  out[o][pos] = relu(bn1(sum_k A[pos][k]*Bw[o][k] + b))
// A = g_vox (k laid out z*64+c), B = g_bw (pre-permuted -> contiguous loads)
// Tile 128(M=pos) x 128(N=o) x 16(K). 256 threads, 8x8 micro, FMA2 over n-pairs.
// 32 stages x 2 syncs. Grid (2, 1250): n-half FASTEST so both n-blocks of a
// pos-tile co-reside and share A through L2.
// Software-pipelined: next stage's A/B (2x float4 each) prefetched into regs;
// their STS lands after the compute loop, so load latency overlaps FMA2.
// ---------------------------------------------------------------------------
__global__ __launch_bounds__(256, 2)
void k_conv1(const float *__restrict__ c1b,
             const float *__restrict__ bn1g, const float *__restrict__ bn1b) {
    __shared__ float As[16][128];
    __shared__ float Bs[16][128];
    const int t   = threadIdx.x;
    const int ty  = t & 15;       // m group: m_local = ty + 16*r
    const int tx  = t >> 4;       // n group: n_local in {tx*4..+3, 64+tx*4..+3}
    const int pos0 = blockIdx.y * 128;
    const int n0   = blockIdx.x * 128;

    float2 acc[8][4];
#pragma unroll
    for (int r = 0; r < 8; r++)
#pragma unroll
        for (int q = 0; q < 4; q++) acc[r][q] = make_float2(0.f, 0.f);

    const int lm  = t >> 1;          // 0..127
    const int lk8 = (t & 1) * 8;     // 0 or 8
    const float *Ag = g_vox + (size_t)(pos0 + lm) * 512 + lk8;
    const float *Bg = g_bw + (size_t)(n0 + lm) * 512 + lk8;

    // prologue prefetch (kt = 0) — contiguous 2x float4 per operand
    float4 av0 = *reinterpret_cast<const float4 *>(Ag);
    float4 av1 = *reinterpret_cast<const float4 *>(Ag + 4);
    float4 bv0 = *reinterpret_cast<const float4 *>(Bg);
    float4 bv1 = *reinterpret_cast<const float4 *>(Bg + 4);

    for (int kt = 0; kt < 32; kt++) {
        As[lk8 + 0][lm] = av0.x; As[lk8 + 1][lm] = av0.y;
        As[lk8 + 2][lm] = av0.z; As[lk8 + 3][lm] = av0.w;
        As[lk8 + 4][lm] = av1.x; As[lk8 + 5][lm] = av1.y;
        As[lk8 + 6][lm] = av1.z; As[lk8 + 7][lm] = av1.w;
        Bs[lk8 + 0][lm] = bv0.x; Bs[lk8 + 1][lm] = bv0.y;
        Bs[lk8 + 2][lm] = bv0.z; Bs[lk8 + 3][lm] = bv0.w;
        Bs[lk8 + 4][lm] = bv1.x; Bs[lk8 + 5][lm] = bv1.y;
        Bs[lk8 + 6][lm] = bv1.z; Bs[lk8 + 7][lm] = bv1.w;
        __syncthreads();

        // prefetch next stage while computing this one
        if (kt < 31) {
            const float *An = Ag + (kt + 1) * 16;
            const float *Bn = Bg + (kt + 1) * 16;
            av0 = *reinterpret_cast<const float4 *>(An);
            av1 = *reinterpret_cast<const float4 *>(An + 4);
            bv0 = *reinterpret_cast<const float4 *>(Bn);
            bv1 = *reinterpret_cast<const float4 *>(Bn + 4);
        }

#pragma unroll
        for (int k = 0; k < 16; k++) {
            float a[8];
#pragma unroll
            for (int r = 0; r < 8; r++) a[r] = As[k][ty + 16 * r];
            float2 b0 = *reinterpret_cast<float2 *>(&Bs[k][tx * 4]);
            float2 b1v = *reinterpret_cast<float2 *>(&Bs[k][tx * 4 + 2]);
            float2 b2v = *reinterpret_cast<float2 *>(&Bs[k][64 + tx * 4]);
            float2 b3v = *reinterpret_cast<float2 *>(&Bs[k][64 + tx * 4 + 2]);
#pragma unroll
            for (int r = 0; r < 8; r++) {
                float2 a2 = make_float2(a[r], a[r]);
                acc[r][0] = ffma2(a2, b0, acc[r][0]);
                acc[r][1] = ffma2(a2, b1v, acc[r][1]);
                acc[r][2] = ffma2(a2, b2v, acc[r][2]);
                acc[r][3] = ffma2(a2, b3v, acc[r][3]);
            }
        }
        __syncthreads();
    }

    const float inv = rsqrtf(1.f + 1e-5f);
    float co[8], sc[8], sb[8];
#pragma unroll
    for (int q = 0; q < 8; q++) {
        int n = n0 + (q < 4 ? tx * 4 + q : 64 + tx * 4 + q - 4);
        co[q] = c1b[n]; sc[q] = bn1g[n] * inv; sb[q] = bn1b[n];
    }
#pragma unroll
    for (int r = 0; r < 8; r++) {
        int m = pos0 + ty + 16 * r;
        float v[8] = {acc[r][0].x, acc[r][0].y, acc[r][1].x, acc[r][1].y,
                      acc[r][2].x, acc[r][2].y, acc[r][3].x, acc[r][3].y};
#pragma unroll
        for (int q = 0; q < 8; q++) {
            int n = n0 + (q < 4 ? tx * 4 + q : 64 + tx * 4 + q - 4);
            g_p1[(size_t)n * NPOS + m] =
                fmaxf(fmaf(v[q] + co[q], sc[q], sb[q]), 0.f);
        }
    }
}

// ---------------------------------------------------------------------------
// Kernel 3: conv2 3x3 + BN + ReLU + fused 2x2 maxpool.
// Spatial tile 32x32 (edge predication), 8 oc per block.
// Grid: (ocg=32 FASTEST, sx=13, sy=13) -> input-tile L2 reuse across oc-groups.
// cp.async double-buffered staging (ICC=4 ping-pong): stage s+1's copies run
// global->smem asynchronously DURING stage s's compute; wait_group 0 + one
// __syncthreads per stage.  OOB halo uses src-size-0 zero-fill.
// 256 thr = 128 spatial (tx:8 x ty:16, each 2h x 4w) x 2 oc-halves (4 oc each).
// ---------------------------------------------------------------------------
#define ICC 4
__global__ __launch_bounds__(256, 2)
void k_conv2(const float *__restrict__ c2w, const float *__restrict__ c2b,
             const float *__restrict__ bn2g, const float *__restrict__ bn2b) {
    __shared__ float sin_[2][ICC][34][36];   // 2 x 19584 B
    __shared__ float swt [2][ICC][8][9];     // 2 x  1152 B   (41.47 KB total)
    const int t  = threadIdx.x;
    const int sp = t & 127;
    const int oh = t >> 7;          // 0..1
    const int tx = sp & 7;          // 0..7  -> cols tx*4 .. +3
    const int ty = sp >> 3;         // 0..15 -> rows ty*2 .. +1
    const int ocg = blockIdx.x * 8;        // fastest: L2 input-tile reuse
    const int x0  = blockIdx.y * 32;
    const int y0  = blockIdx.z * 32;

    float2 acc[4][4];               // [oc_local 0..3][dy*2 + pair]
#pragma unroll
    for (int j = 0; j < 4; j++)
#pragma unroll
        for (int q = 0; q < 4; q++) acc[j][q] = make_float2(0.f, 0.f);

    auto issue_stage = [&](int icc, int buf) {
#pragma unroll 4
        for (int idx = t; idx < ICC * 34 * 34; idx += 256) {
            int ic  = idx / 1156;
            int rem = idx - ic * 1156;
            int r = rem / 34, c = rem - r * 34;
            int gy = y0 - 1 + r, gx = x0 - 1 + c;
            bool ok = (gy >= 0 && gy < 400 && gx >= 0 && gx < 400);
            const float *src = ok ? &g_p1[(size_t)(icc + ic) * NPOS + gy * 400 + gx]
                                  : g_p1;            // clamped; 0 bytes read
            cp_async4(smem_u32(&sin_[buf][ic][r][c]), src, ok ? 4 : 0);
        }
        for (int idx = t; idx < ICC * 72; idx += 256) {
            int ic  = idx / 72;
            int rem = idx - ic * 72;
            int o = rem / 9, tap = rem - o * 9;
            cp_async4(smem_u32(&swt[buf][ic][o][tap]),
                      &c2w[((size_t)(ocg + o) * 256 + icc + ic) * 9 + tap], 4);
        }
        asm volatile("cp.async.commit_group;");
    };

    issue_stage(0, 0);
    asm volatile("cp.async.wait_group 0;");
    __syncthreads();

    for (int s = 0; s < 64; s++) {          // 64 stages x ICC=4 ics = 256
        const int buf = s & 1;
        // safe: all warps passed the barrier ending stage s-1, the last reader
        // of buf^1; copies overlap this stage's compute below.
        if (s < 63) issue_stage((s + 1) * ICC, buf ^ 1);

#pragma unroll
        for (int ic = 0; ic < ICC; ic++) {
            // 4x6 input patch as overlapping x-pairs: pr[row][pair-start 0..4]
            float2 pr[4][5];
#pragma unroll
            for (int r = 0; r < 4; r++) {
                const float *row = &sin_[buf][ic][ty * 2 + r][tx * 4];
                float2 e0 = *reinterpret_cast<const float2 *>(row);
                float2 e1 = *reinterpret_cast<const float2 *>(row + 2);
                float2 e2 = *reinterpret_cast<const float2 *>(row + 4);
                pr[r][0] = e0;
                pr[r][1] = make_float2(e0.y, e1.x);
                pr[r][2] = e1;
                pr[r][3] = make_float2(e1.y, e2.x);
                pr[r][4] = e2;
            }
#pragma unroll
            for (int j = 0; j < 4; j++) {
                const int ol = oh * 4 + j;
#pragma unroll
                for (int ky = 0; ky < 3; ky++) {
#pragma unroll
                    for (int kx = 0; kx < 3; kx++) {
                        float w = swt[buf][ic][ol][ky * 3 + kx];
                        float2 w2 = make_float2(w, w);
                        acc[j][0] = ffma2(pr[ky + 0][kx + 0], w2, acc[j][0]);
                        acc[j][1] = ffma2(pr[ky + 0][kx + 2], w2, acc[j][1]);
                        acc[j][2] = ffma2(pr[ky + 1][kx + 0], w2, acc[j][2]);
                        acc[j][3] = ffma2(pr[ky + 1][kx + 2], w2, acc[j][3]);
                    }
                }
            }
        }
        if (s < 63) asm volatile("cp.async.wait_group 0;");
        __syncthreads();
    }

    // epilogue: bias + BN + ReLU, 2x2 maxpool (thread-local), predicated store
    const float inv = rsqrtf(1.f + 1e-5f);
    const int py = (y0 >> 1) + ty;
    const int pxb = (x0 >> 1) + tx * 2;
#pragma unroll
    for (int j = 0; j < 4; j++) {
        const int oc = ocg + oh * 4 + j;
        const float bb = c2b[oc], sc = bn2g[oc] * inv, sb = bn2b[oc];
#pragma unroll
        for (int p = 0; p < 2; p++) {
            float e0 = fmaxf(fmaf(acc[j][p].x + bb, sc, sb), 0.f);
            float e1 = fmaxf(fmaf(acc[j][p].y + bb, sc, sb), 0.f);
            float e2 = fmaxf(fmaf(acc[j][2 + p].x + bb, sc, sb), 0.f);
            float e3 = fmaxf(fmaf(acc[j][2 + p].y + bb, sc, sb), 0.f);
            float m = fmaxf(fmaxf(e0, e1), fmaxf(e2, e3));
            int px = pxb + p;
            if (py < 200 && px < 200)
                g_pool[(size_t)oc * PPOS + py * 200 + px] = m;
        }
    }
}

// ---------------------------------------------------------------------------
// Kernel 4: concat(bev[80], pooled-as-[32][...][8]) -> 1x1x1 conv (112->80)
//           + BN + residual ReLU.  64 positions/block staged in shared;
//           weights read as float2 c-pairs (half the hot loads, same order).
// ---------------------------------------------------------------------------
__global__ __launch_bounds__(256)
void k_final(const float *__restrict__ bev,
             const float *__restrict__ c3w, const float *__restrict__ c3b,
             const float *__restrict__ bn3g, const float *__restrict__ bn3b,
             float *__restrict__ out) {
    __shared__ __align__(16) float sx[112][64];
    const int t = threadIdx.x;
    const int pos0 = blockIdx.x * 64;

#pragma unroll 4
    for (int idx = t; idx < 112 * 64; idx += 256) {
        int c = idx >> 6;
        int p = idx & 63;
        int pos = pos0 + p;
        float v;
        if (c < 80) {
            v = bev[(size_t)c * OUTPOS + pos];
        } else {
            int c32 = c - 80;
            int h = pos / 1600;
            int w = (pos >> 3) % 200;
            int z = pos & 7;
            v = g_pool[(size_t)(c32 * 8 + z) * PPOS + h * 200 + w];
        }
        sx[c][p] = v;
    }
    __syncthreads();

    const int og = t >> 4;   // 0..15 -> o = og*5 + j
    const int pg = t & 15;   // 0..15 -> pos = pg*4 .. +3
    float2 acc[5][2];
#pragma unroll
    for (int j = 0; j < 5; j++) { acc[j][0] = make_float2(0.f, 0.f); acc[j][1] = make_float2(0.f, 0.f); }

#pragma unroll 2
    for (int c = 0; c < 112; c += 2) {
        float4 xv0 = *reinterpret_cast<const float4 *>(&sx[c][pg * 4]);
        float4 xv1 = *reinterpret_cast<const float4 *>(&sx[c + 1][pg * 4]);
        float2 xa0 = make_float2(xv0.x, xv0.y), xb0 = make_float2(xv0.z, xv0.w);
        float2 xa1 = make_float2(xv1.x, xv1.y), xb1 = make_float2(xv1.z, xv1.w);
#pragma unroll
        for (int j = 0; j < 5; j++) {
            float2 wp = *reinterpret_cast<const float2 *>(
                &c3w[(og * 5 + j) * 112 + c]);
            float2 w0 = make_float2(wp.x, wp.x);
            float2 w1 = make_float2(wp.y, wp.y);
            acc[j][0] = ffma2(xa0, w0, acc[j][0]);
            acc[j][1] = ffma2(xb0, w0, acc[j][1]);
            acc[j][0] = ffma2(xa1, w1, acc[j][0]);
            acc[j][1] = ffma2(xb1, w1, acc[j][1]);
        }
    }

    const float inv = rsqrtf(1.f + 1e-5f);
#pragma unroll
    for (int j = 0; j < 5; j++) {
        const int o = og * 5 + j;
        const float bb = c3b[o], sc = bn3g[o] * inv, sb = bn3b[o];
        const float *bv = &sx[o][pg * 4];   // o < 80: bev channel (residual)
        float4 r;
        r.x = fmaxf(fmaf(acc[j][0].x + bb, sc, sb) + bv[0], 0.f);
        r.y = fmaxf(fmaf(acc[j][0].y + bb, sc, sb) + bv[1], 0.f);
        r.z = fmaxf(fmaf(acc[j][1].x + bb, sc, sb) + bv[2], 0.f);
        r.w = fmaxf(fmaf(acc[j][1].y + bb, sc, sb) + bv[3], 0.f);
        *reinterpret_cast<float4 *>(&out[(size_t)o * OUTPOS + pos0 + pg * 4]) = r;
    }
}

// ---------------------------------------------------------------------------
extern "C" void kernel_launch(void *const *d_in, const int *in_sizes, int n_in,
                              void *d_out, int out_size) {
    const float *bev  = (const float *)d_in[0];
    const float *pf   = (const float *)d_in[1];
    const int   *pc   = (const int   *)d_in[2];
    const float *W1   = (const float *)d_in[3];
    const float *b1   = (const float *)d_in[4];
    const float *W2   = (const float *)d_in[5];
    const float *b2   = (const float *)d_in[6];
    const float *c1w  = (const float *)d_in[7];
    const float *c1b  = (const float *)d_in[8];
    const float *bn1g = (const float *)d_in[9];
    const float *bn1b = (const float *)d_in[10];
    const float *c2w  = (const float *)d_in[11];
    const float *c2b  = (const float *)d_in[12];
    const float *bn2g = (const float *)d_in[13];
    const float *bn2b = (const float *)d_in[14];
    const float *c3w  = (const float *)d_in[15];
    const float *c3b  = (const float *)d_in[16];
    const float *bn3g = (const float *)d_in[17];
    const float *bn3b = (const float *)d_in[18];
    float *out = (float *)d_out;
    const int N = in_sizes[1] / 68;   // 200000

    k_zero_permw<<<80512, 256>>>(c1w);      // zero g_vox + build g_bw, one launch
    k_mlp_scatter<<<(N + 3) / 4, 256>>>(pf, pc, W1, b1, W2, b2, N);
    k_conv1<<<dim3(2, 1250), 256>>>(c1b, bn1g, bn1b);
    k_conv2<<<dim3(32, 13, 13), 256>>>(c2w, c2b, bn2g, bn2b);
    k_final<<<5000, 256>>>(bev, c3w, c3b, bn3g, bn3b, out);
}

// round 15
// speedup vs baseline: 1.1409x; 1.1409x over previous
#include <cuda_runtime.h>
#include <cstdint>

// ---------------------------------------------------------------------------
// PriorFusion3D_voxel — fp32 SIMT pipeline with packed f32x2 FMA (sm_103a)
//
// R10 measured: 7406us total, conv2 ~6.0ms with alu=59.5% > fma=49.9% —
// staging address math recomputed per stage (div/mod flood) + per-tap
// (w,w) pair-dup MOVs were stealing the issue slots.  R11-R15: hoist all
// stage-invariant staging offsets into registers; stage weights duplicated
// into smem as float2 (w,w) so the FFMA2 operand is one broadcast LDS.64.
//
// Pipeline:
//   0) zero voxel grid + permute conv1 weights (single fused launch)
//   1) per-point MLP (68->64->64) + scatter -> g_vox
//   2) conv1 1x1 (512->256) +BN+ReLU (GEMM) -> g_p1  [256][400*400]
//   3) conv2 3x3 (256->256) +BN+ReLU + fused 2x2 maxpool -> g_pool
//      oc-group FASTEST grid (DRAM=0.4% measured: L2 reuse works) + cp.async
//   4) concat(bev, pooled) -> 1x1x1 conv (112->80) +BN + residual ReLU
// ---------------------------------------------------------------------------

#define NPOS   160000      // 400*400
#define PPOS   40000       // 200*200
#define OUTPOS 320000      // 200*200*8

__device__ __align__(16) float g_vox[400 * 400 * 512];    // 327.68 MB
__device__ __align__(16) float g_p1 [256 * NPOS];         // 163.84 MB
__device__ __align__(16) float g_pool[256 * PPOS];        //  40.96 MB
__device__ __align__(16) float g_bw [256 * 512];          //   0.52 MB (permuted c1w)

__device__ __forceinline__ float2 ffma2(float2 a, float2 b, float2 c) {
    float2 d;
    asm("fma.rn.f32x2 %0, %1, %2, %3;"
        : "=l"(reinterpret_cast<unsigned long long &>(d))
        : "l"(reinterpret_cast<unsigned long long &>(a)),
          "l"(reinterpret_cast<unsigned long long &>(b)),
          "l"(reinterpret_cast<unsigned long long &>(c)));
    return d;
}

__device__ __forceinline__ uint32_t smem_u32(const void *p) {
    return (uint32_t)__cvta_generic_to_shared(p);
}
// 4-byte async copy; src_bytes = 0 -> zero-fill (no global read per PTX spec)
__device__ __forceinline__ void cp_async4(uint32_t dst, const void *src, int src_bytes) {
    asm volatile("cp.async.ca.shared.global [%0], [%1], 4, %2;"
                 :: "r"(dst), "l"(src), "r"(src_bytes));
}

// ---------------------------------------------------------------------------
// Kernel 0 (fused): blocks [0, 80000) zero the voxel grid; blocks
// [80000, 80512) permute conv1 weights into k-contiguous order:
//   g_bw[o][kk] = c1w[o][(kk&63)*8 + (kk>>6)]   (kk = z*64+c voxel k-order)
// ---------------------------------------------------------------------------
__global__ void k_zero_permw(const float *__restrict__ c1w) {
    if (blockIdx.x < 80000) {
        size_t i = ((size_t)blockIdx.x * blockDim.x + threadIdx.x) * 4;
        *reinterpret_cast<float4 *>(&g_vox[i]) = make_float4(0.f, 0.f, 0.f, 0.f);
    } else {
        int idx = (blockIdx.x - 80000) * 256 + threadIdx.x;   // 0 .. 131071
        int o  = idx >> 9;
        int kk = idx & 511;
        g_bw[idx] = c1w[(o << 9) + ((kk & 63) << 3) + (kk >> 6)];
    }
}

// ---------------------------------------------------------------------------
// Kernel 1: per-point MLP + scatter.  4 points/block, 64 threads/point.
// vox layout: g_vox[(cy*400+cx)*512 + cz*64 + c]
// ---------------------------------------------------------------------------
__global__ void k_mlp_scatter(const float *__restrict__ pf,
                              const int   *__restrict__ pc,
                              const float *__restrict__ W1,
                              const float *__restrict__ b1,
                              const float *__restrict__ W2,
                              const float *__restrict__ b2,
                              int N) {
    __shared__ float sx[4][68];
    __shared__ float sh[4][64];
    const int pt = threadIdx.x >> 6;
    const int j  = threadIdx.x & 63;
    const int p  = blockIdx.x * 4 + pt;
    const bool valid = (p < N);

    if (valid) {
        for (int i = j; i < 68; i += 64) sx[pt][i] = pf[p * 68 + i];
    }
    __syncthreads();

    float h1 = b1[j];
#pragma unroll
    for (int i = 0; i < 68; i++) h1 = fmaf(sx[pt][i], W1[i * 64 + j], h1);
    sh[pt][j] = fmaxf(h1, 0.f);
    __syncthreads();

    if (!valid) return;
    float h2 = b2[j];
#pragma unroll
    for (int i = 0; i < 64; i++) h2 = fmaf(sh[pt][i], W2[i * 64 + j], h2);
    h2 = fmaxf(h2, 0.f);

    const int cx = pc[p * 3 + 0], cy = pc[p * 3 + 1], cz = pc[p * 3 + 2];
    g_vox[((size_t)(cy * 400 + cx)) * 512 + cz * 64 + j] = h2;
}

// ---------------------------------------------------------------------------
// Kernel 2: conv1 as SGEMM  out[o][pos] = relu(bn1(sum_k A[pos][k]*Bw[o][k] + b))
// Tile 128x128x16, 256 threads, 8x8 micro, FMA2 over n-pairs, reg-pipelined.
// Grid (2, 1250): n-half FASTEST so both n-blocks of a pos-tile share A via L2.
// ---------------------------------------------------------------------------
__global__ __launch_bounds__(256, 2)
void k_conv1(const float *__restrict__ c1b,
             const float *__restrict__ bn1g, const float *__restrict__ bn1b) {
    __shared__ float As[16][128];
    __shared__ float Bs[16][128];
    const int t   = threadIdx.x;
    const int ty  = t & 15;       // m group: m_local = ty + 16*r
    const int tx  = t >> 4;       // n group: n_local in {tx*4..+3, 64+tx*4..+3}
    const int pos0 = blockIdx.y * 128;
    const int n0   = blockIdx.x * 128;

    float2 acc[8][4];
#pragma unroll
    for (int r = 0; r < 8; r++)
#pragma unroll
        for (int q = 0; q < 4; q++) acc[r][q] = make_float2(0.f, 0.f);

    const int lm  = t >> 1;          // 0..127
    const int lk8 = (t & 1) * 8;     // 0 or 8
    const float *Ag = g_vox + (size_t)(pos0 + lm) * 512 + lk8;
    const float *Bg = g_bw + (size_t)(n0 + lm) * 512 + lk8;

    float4 av0 = *reinterpret_cast<const float4 *>(Ag);
    float4 av1 = *reinterpret_cast<const float4 *>(Ag + 4);
    float4 bv0 = *reinterpret_cast<const float4 *>(Bg);
    float4 bv1 = *reinterpret_cast<const float4 *>(Bg + 4);

    for (int kt = 0; kt < 32; kt++) {
        As[lk8 + 0][lm] = av0.x; As[lk8 + 1][lm] = av0.y;
        As[lk8 + 2][lm] = av0.z; As[lk8 + 3][lm] = av0.w;
        As[lk8 + 4][lm] = av1.x; As[lk8 + 5][lm] = av1.y;
        As[lk8 + 6][lm] = av1.z; As[lk8 + 7][lm] = av1.w;
        Bs[lk8 + 0][lm] = bv0.x; Bs[lk8 + 1][lm] = bv0.y;
        Bs[lk8 + 2][lm] = bv0.z; Bs[lk8 + 3][lm] = bv0.w;
        Bs[lk8 + 4][lm] = bv1.x; Bs[lk8 + 5][lm] = bv1.y;
        Bs[lk8 + 6][lm] = bv1.z; Bs[lk8 + 7][lm] = bv1.w;
        __syncthreads();

        if (kt < 31) {
            const float *An = Ag + (kt + 1) * 16;
            const float *Bn = Bg + (kt + 1) * 16;
            av0 = *reinterpret_cast<const float4 *>(An);
            av1 = *reinterpret_cast<const float4 *>(An + 4);
            bv0 = *reinterpret_cast<const float4 *>(Bn);
            bv1 = *reinterpret_cast<const float4 *>(Bn + 4);
        }

#pragma unroll
        for (int k = 0; k < 16; k++) {
            float a[8];
#pragma unroll
            for (int r = 0; r < 8; r++) a[r] = As[k][ty + 16 * r];
            float2 b0 = *reinterpret_cast<float2 *>(&Bs[k][tx * 4]);
            float2 b1v = *reinterpret_cast<float2 *>(&Bs[k][tx * 4 + 2]);
            float2 b2v = *reinterpret_cast<float2 *>(&Bs[k][64 + tx * 4]);
            float2 b3v = *reinterpret_cast<float2 *>(&Bs[k][64 + tx * 4 + 2]);
#pragma unroll
            for (int r = 0; r < 8; r++) {
                float2 a2 = make_float2(a[r], a[r]);
                acc[r][0] = ffma2(a2, b0, acc[r][0]);
                acc[r][1] = ffma2(a2, b1v, acc[r][1]);
                acc[r][2] = ffma2(a2, b2v, acc[r][2]);
                acc[r][3] = ffma2(a2, b3v, acc[r][3]);
            }
        }
        __syncthreads();
    }

    const float inv = rsqrtf(1.f + 1e-5f);
    float co[8], sc[8], sb[8];
#pragma unroll
    for (int q = 0; q < 8; q++) {
        int n = n0 + (q < 4 ? tx * 4 + q : 64 + tx * 4 + q - 4);
        co[q] = c1b[n]; sc[q] = bn1g[n] * inv; sb[q] = bn1b[n];
    }
#pragma unroll
    for (int r = 0; r < 8; r++) {
        int m = pos0 + ty + 16 * r;
        float v[8] = {acc[r][0].x, acc[r][0].y, acc[r][1].x, acc[r][1].y,
                      acc[r][2].x, acc[r][2].y, acc[r][3].x, acc[r][3].y};
#pragma unroll
        for (int q = 0; q < 8; q++) {
            int n = n0 + (q < 4 ? tx * 4 + q : 64 + tx * 4 + q - 4);
            g_p1[(size_t)n * NPOS + m] =
                fmaxf(fmaf(v[q] + co[q], sc[q], sb[q]), 0.f);
        }
    }
}

// ---------------------------------------------------------------------------
// Kernel 3: conv2 3x3 + BN + ReLU + fused 2x2 maxpool.
// All staging offsets precomputed ONCE per thread (no per-stage div/mod);
// weights staged DUPLICATED into smem float2 (w,w) so the FFMA2 b-operand is
// a single broadcast LDS.64 (no per-tap MOV pair-building).
// Grid (32 ocg FASTEST, 13, 13); cp.async ping-pong (ICC=4), 1 barrier/stage.
// ---------------------------------------------------------------------------
#define ICC 4
__global__ __launch_bounds__(256, 2)
void k_conv2(const float *__restrict__ c2w, const float *__restrict__ c2b,
             const float *__restrict__ bn2g, const float *__restrict__ bn2b) {
    __shared__ float  sin_[2][ICC][34][36];          // 2 x 19584 B
    __shared__ __align__(8) float2 swtd[2][ICC][9][8]; // (w,w) pairs, 2 x 2304 B
    const int t  = threadIdx.x;
    const int sp = t & 127;
    const int oh = t >> 7;          // 0..1
    const int tx = sp & 7;          // 0..7  -> cols tx*4 .. +3
    const int ty = sp >> 3;         // 0..15 -> rows ty*2 .. +1
    const int ocg = blockIdx.x * 8;        // fastest: L2 input-tile reuse
    const int x0  = blockIdx.y * 32;
    const int y0  = blockIdx.z * 32;

    // ---- stage-invariant staging offsets (computed once) ----
    // input: per ic-plane, element idx2 = t + it*256 in [0, 34*34); 5 slots
    int soffB[5], goffB[5], nb[5];
#pragma unroll
    for (int it = 0; it < 5; it++) {
        int idx2 = t + it * 256;
        int r = idx2 / 34, c = idx2 - r * 34;
        int gy = y0 - 1 + r, gx = x0 - 1 + c;
        bool ok = (gy >= 0 && gy < 400 && gx >= 0 && gx < 400);
        soffB[it] = (r * 36 + c) * 4;
        goffB[it] = ok ? (gy * 400 + gx) * 4 : 0;
        nb[it]    = ok ? 4 : 0;
    }
    // weights: element e = t + s2*256 in [0, ICC*8*9=288); 2 slots
    int wgoB[2], wdstB[2];
#pragma unroll
    for (int s2 = 0; s2 < 2; s2++) {
        int e = t + s2 * 256;
        int ew = (e < 288) ? e : 0;
        int icw = ew / 72, rw = ew - icw * 72;
        int o = rw / 9, tap = rw - o * 9;
        wgoB[s2]  = ((ocg + o) * 2304 + icw * 9 + tap) * 4;   // gmem bytes
        wdstB[s2] = ((icw * 9 + tap) * 8 + o) * 8;            // smem bytes
    }

    const uint32_t sin0 = smem_u32(&sin_[0][0][0][0]);
    const uint32_t swd0 = smem_u32(&swtd[0][0][0][0]);

    float2 acc[4][4];               // [oc_local 0..3][dy*2 + pair]
#pragma unroll
    for (int j = 0; j < 4; j++)
#pragma unroll
        for (int q = 0; q < 4; q++) acc[j][q] = make_float2(0.f, 0.f);

    auto issue_stage = [&](int icc, int buf) {
        const char *g1 = (const char *)g_p1 + (size_t)icc * (NPOS * 4);
        const char *cw = (const char *)c2w + (size_t)icc * 36;   // +icc*9 floats
        const uint32_t sb = sin0 + buf * 19584;
        const uint32_t wb = swd0 + buf * 2304;
#pragma unroll
        for (int ic = 0; ic < ICC; ic++) {
            const char *gpi = g1 + (size_t)ic * (NPOS * 4);
            const uint32_t sbi = sb + ic * 4896;                 // 34*36*4
#pragma unroll
            for (int it = 0; it < 4; it++)
                cp_async4(sbi + soffB[it], gpi + goffB[it], nb[it]);
            if (t < 132)   // idx2 = t+1024 < 1156
                cp_async4(sbi + soffB[4], gpi + goffB[4], nb[4]);
        }
        // weights duplicated: (w,w) via two 4B copies of the same source
        cp_async4(wb + wdstB[0],     cw + wgoB[0], 4);
        cp_async4(wb + wdstB[0] + 4, cw + wgoB[0], 4);
        if (t < 32) {      // e = t+256 < 288
            cp_async4(wb + wdstB[1],     cw + wgoB[1], 4);
            cp_async4(wb + wdstB[1] + 4, cw + wgoB[1], 4);
        }
        asm volatile("cp.async.commit_group;");
    };

    issue_stage(0, 0);
    asm volatile("cp.async.wait_group 0;");
    __syncthreads();

    for (int s = 0; s < 64; s++) {          // 64 stages x ICC=4 ics = 256
        const int buf = s & 1;
        if (s < 63) issue_stage((s + 1) * ICC, buf ^ 1);

#pragma unroll
        for (int ic = 0; ic < ICC; ic++) {
            // 4x6 input patch as overlapping x-pairs: pr[row][pair-start 0..4]
            float2 pr[4][5];
#pragma unroll
            for (int r = 0; r < 4; r++) {
                const float *row = &sin_[buf][ic][ty * 2 + r][tx * 4];
                float2 e0 = *reinterpret_cast<const float2 *>(row);
                float2 e1 = *reinterpret_cast<const float2 *>(row + 2);
                float2 e2 = *reinterpret_cast<const float2 *>(row + 4);
                pr[r][0] = e0;
                pr[r][1] = make_float2(e0.y, e1.x);
                pr[r][2] = e1;
                pr[r][3] = make_float2(e1.y, e2.x);
                pr[r][4] = e2;
            }
#pragma unroll
            for (int j = 0; j < 4; j++) {
                const int ol = oh * 4 + j;
                const float2 *wt = &swtd[buf][ic][0][ol];   // stride 8 float2/tap
#pragma unroll
                for (int ky = 0; ky < 3; ky++) {
#pragma unroll
                    for (int kx = 0; kx < 3; kx++) {
                        float2 w2 = wt[(ky * 3 + kx) * 8];  // broadcast LDS.64
                        acc[j][0] = ffma2(pr[ky + 0][kx + 0], w2, acc[j][0]);
                        acc[j][1] = ffma2(pr[ky + 0][kx + 2], w2, acc[j][1]);
                        acc[j][2] = ffma2(pr[ky + 1][kx + 0], w2, acc[j][2]);
                        acc[j][3] = ffma2(pr[ky + 1][kx + 2], w2, acc[j][3]);
                    }
                }
            }
        }
        if (s < 63) asm volatile("cp.async.wait_group 0;");
        __syncthreads();
    }

    // epilogue: bias + BN + ReLU, 2x2 maxpool (thread-local), predicated store
    const float inv = rsqrtf(1.f + 1e-5f);
    const int py = (y0 >> 1) + ty;
    const int pxb = (x0 >> 1) + tx * 2;
#pragma unroll
    for (int j = 0; j < 4; j++) {
        const int oc = ocg + oh * 4 + j;
        const float bb = c2b[oc], sc = bn2g[oc] * inv, sb = bn2b[oc];
#pragma unroll
        for (int p = 0; p < 2; p++) {
            float e0 = fmaxf(fmaf(acc[j][p].x + bb, sc, sb), 0.f);
            float e1 = fmaxf(fmaf(acc[j][p].y + bb, sc, sb), 0.f);
            float e2 = fmaxf(fmaf(acc[j][2 + p].x + bb, sc, sb), 0.f);
            float e3 = fmaxf(fmaf(acc[j][2 + p].y + bb, sc, sb), 0.f);
            float m = fmaxf(fmaxf(e0, e1), fmaxf(e2, e3));
            int px = pxb + p;
            if (py < 200 && px < 200)
                g_pool[(size_t)oc * PPOS + py * 200 + px] = m;
        }
    }
}

// ---------------------------------------------------------------------------
// Kernel 4: concat(bev[80], pooled-as-[32][...][8]) -> 1x1x1 conv (112->80)
//           + BN + residual ReLU.
// ---------------------------------------------------------------------------
__global__ __launch_bounds__(256)
void k_final(const float *__restrict__ bev,
             const float *__restrict__ c3w, const float *__restrict__ c3b,
             const float *__restrict__ bn3g, const float *__restrict__ bn3b,
             float *__restrict__ out) {
    __shared__ __align__(16) float sx[112][64];
    const int t = threadIdx.x;
    const int pos0 = blockIdx.x * 64;

#pragma unroll 4
    for (int idx = t; idx < 112 * 64; idx += 256) {
        int c = idx >> 6;
        int p = idx & 63;
        int pos = pos0 + p;
        float v;
        if (c < 80) {
            v = bev[(size_t)c * OUTPOS + pos];
        } else {
            int c32 = c - 80;
            int h = pos / 1600;
            int w = (pos >> 3) % 200;
            int z = pos & 7;
            v = g_pool[(size_t)(c32 * 8 + z) * PPOS + h * 200 + w];
        }
        sx[c][p] = v;
    }
    __syncthreads();

    const int og = t >> 4;   // 0..15 -> o = og*5 + j
    const int pg = t & 15;   // 0..15 -> pos = pg*4 .. +3
    float2 acc[5][2];
#pragma unroll
    for (int j = 0; j < 5; j++) { acc[j][0] = make_float2(0.f, 0.f); acc[j][1] = make_float2(0.f, 0.f); }

#pragma unroll 2
    for (int c = 0; c < 112; c += 2) {
        float4 xv0 = *reinterpret_cast<const float4 *>(&sx[c][pg * 4]);
        float4 xv1 = *reinterpret_cast<const float4 *>(&sx[c + 1][pg * 4]);
        float2 xa0 = make_float2(xv0.x, xv0.y), xb0 = make_float2(xv0.z, xv0.w);
        float2 xa1 = make_float2(xv1.x, xv1.y), xb1 = make_float2(xv1.z, xv1.w);
#pragma unroll
        for (int j = 0; j < 5; j++) {
            float2 wp = *reinterpret_cast<const float2 *>(
                &c3w[(og * 5 + j) * 112 + c]);
            float2 w0 = make_float2(wp.x, wp.x);
            float2 w1 = make_float2(wp.y, wp.y);
            acc[j][0] = ffma2(xa0, w0, acc[j][0]);
            acc[j][1] = ffma2(xb0, w0, acc[j][1]);
            acc[j][0] = ffma2(xa1, w1, acc[j][0]);
            acc[j][1] = ffma2(xb1, w1, acc[j][1]);
        }
    }

    const float inv = rsqrtf(1.f + 1e-5f);
#pragma unroll
    for (int j = 0; j < 5; j++) {
        const int o = og * 5 + j;
        const float bb = c3b[o], sc = bn3g[o] * inv, sb = bn3b[o];
        const float *bv = &sx[o][pg * 4];   // o < 80: bev channel (residual)
        float4 r;
        r.x = fmaxf(fmaf(acc[j][0].x + bb, sc, sb) + bv[0], 0.f);
        r.y = fmaxf(fmaf(acc[j][0].y + bb, sc, sb) + bv[1], 0.f);
        r.z = fmaxf(fmaf(acc[j][1].x + bb, sc, sb) + bv[2], 0.f);
        r.w = fmaxf(fmaf(acc[j][1].y + bb, sc, sb) + bv[3], 0.f);
        *reinterpret_cast<float4 *>(&out[(size_t)o * OUTPOS + pos0 + pg * 4]) = r;
    }
}

// ---------------------------------------------------------------------------
extern "C" void kernel_launch(void *const *d_in, const int *in_sizes, int n_in,
                              void *d_out, int out_size) {
    const float *bev  = (const float *)d_in[0];
    const float *pf   = (const float *)d_in[1];
    const int   *pc   = (const int   *)d_in[2];
    const float *W1   = (const float *)d_in[3];
    const float *b1   = (const float *)d_in[4];
    const float *W2   = (const float *)d_in[5];
    const float *b2   = (const float *)d_in[6];
    const float *c1w  = (const float *)d_in[7];
    const float *c1b  = (const float *)d_in[8];
    const float *bn1g = (const float *)d_in[9];
    const float *bn1b = (const float *)d_in[10];
    const float *c2w  = (const float *)d_in[11];
    const float *c2b  = (const float *)d_in[12];
    const float *bn2g = (const float *)d_in[13];
    const float *bn2b = (const float *)d_in[14];
    const float *c3w  = (const float *)d_in[15];
    const float *c3b  = (const float *)d_in[16];
    const float *bn3g = (const float *)d_in[17];
    const float *bn3b = (const float *)d_in[18];
    float *out = (float *)d_out;
    const int N = in_sizes[1] / 68;   // 200000

    k_zero_permw<<<80512, 256>>>(c1w);      // zero g_vox + build g_bw
    k_mlp_scatter<<<(N + 3) / 4, 256>>>(pf, pc, W1, b1, W2, b2, N);
    k_conv1<<<dim3(2, 1250), 256>>>(c1b, bn1g, bn1b);
    k_conv2<<<dim3(32, 13, 13), 256>>>(c2w, c2b, bn2g, bn2b);
    k_final<<<5000, 256>>>(bev, c3w, c3b, bn3g, bn3b, out);
}